// round 11
// baseline (speedup 1.0000x reference)
#include <cuda_runtime.h>
#include <cuda_bf16.h>
#include <math.h>

// Problem constants
#define BB 2
#define TT 512
#define HH 128
#define EE 32
#define VV 32000
#define NN (BB*TT)          // 1024

#define LOGITS_ELEMS ((long long)BB*TT*VV)   // 32768000
#define HID_OFF LOGITS_ELEMS
#define W_OFF   (LOGITS_ELEMS + (long long)BB*HH)  // 32768256

// -------------------- scratch (device globals; no allocation allowed) ------
__device__ float g_xp  [NN*HH];
__device__ float g_rnn [NN*HH];
__device__ float g_q   [NN*HH];
__device__ float g_k   [NN*HH];
__device__ float g_ctx [NN*HH];
__device__ float g_out2[NN*HH];
__device__ int   g_is64;

// -------------------- packed f32x2 helpers ---------------------------------
__device__ __forceinline__ unsigned long long pack2(float lo, float hi) {
    unsigned long long r;
    asm("mov.b64 %0, {%1,%2};" : "=l"(r) : "f"(lo), "f"(hi));
    return r;
}
__device__ __forceinline__ unsigned long long fma2(unsigned long long a,
                                                   unsigned long long b,
                                                   unsigned long long c) {
    unsigned long long d;
    asm("fma.rn.f32x2 %0, %1, %2, %3;" : "=l"(d) : "l"(a), "l"(b), "l"(c));
    return d;
}
__device__ __forceinline__ unsigned long long add2(unsigned long long a,
                                                   unsigned long long b) {
    unsigned long long d;
    asm("add.rn.f32x2 %0, %1, %2;" : "=l"(d) : "l"(a), "l"(b));
    return d;
}
__device__ __forceinline__ float2 unpack2(unsigned long long v) {
    float2 f;
    asm("mov.b64 {%0,%1}, %2;" : "=f"(f.x), "=f"(f.y) : "l"(v));
    return f;
}

// -------------------- K0: detect int64 vs int32 storage of x ---------------
// int64 storage: int32 view odd words (high halves) are all 0.
// int32 storage: odd words are uniform values in [0,32000) -> P(all zero)~0.
// Only touches the first 4KB (valid for both layouts).
__global__ void k_detect(const int* __restrict__ x32) {
    int tid = threadIdx.x;
    int bad = 0;
    for (int j = tid; j < 512; j += 32)
        if (x32[2*j + 1] != 0) bad = 1;
    unsigned m = __ballot_sync(0xffffffffu, bad);
    if (tid == 0) g_is64 = (m == 0) ? 1 : 0;
}

// -------------------- K1: embedding gather + input projection --------------
// xp[n,i] = sum_e emb[x[n],e]*W_ih[i,e] + b_ih[i] + b_hh[i]
__global__ void k_embed(const void* __restrict__ x,
                        const float* __restrict__ emb_t,
                        const float* __restrict__ W_ih,
                        const float* __restrict__ b_ih,
                        const float* __restrict__ b_hh) {
    int n = blockIdx.x;
    int i = threadIdx.x;
    __shared__ __align__(16) float e_sh[EE];
    if (i < EE) {
        long long idx = g_is64 ? ((const long long*)x)[n]
                               : (long long)((const int*)x)[n];
        e_sh[i] = emb_t[idx * EE + i];
    }
    __syncthreads();
    float acc = b_ih[i] + b_hh[i];
    const float4* w = (const float4*)(W_ih + i * EE);
#pragma unroll
    for (int u = 0; u < EE/4; u++) {
        float4 wv = w[u];
        acc += wv.x * e_sh[4*u+0] + wv.y * e_sh[4*u+1]
             + wv.z * e_sh[4*u+2] + wv.w * e_sh[4*u+3];
    }
    g_xp[n * HH + i] = acc;
}

// -------------------- K2: sequential RNN scan -------------------------------
// grid(2) — one CTA per batch element.  block(512): 128 outputs x 4 lanes.
// h_new[i] = tanh(xp[t,i] + sum_j h[j]*W_hh[i,j])
__global__ void k_rnn(const float* __restrict__ W_hh,
                      const float* __restrict__ hidden,
                      float* __restrict__ hid_out) {
    int b   = blockIdx.x;
    int tid = threadIdx.x;
    int i   = tid >> 2;       // output index 0..127
    int q   = tid & 3;        // lane within output (32 MACs each)

    __shared__ __align__(16) float h_sh[2][HH];

    // W_hh[i, q*32 .. q*32+31] packed as 16 f32x2 (float2 bit layout == f32x2)
    const unsigned long long* wrow =
        reinterpret_cast<const unsigned long long*>(W_hh + i*HH + q*32);
    unsigned long long wv[16];
#pragma unroll
    for (int r = 0; r < 16; r++) wv[r] = wrow[r];

    if (q == 0) h_sh[0][i] = hidden[b*HH + i];
    __syncthreads();

    float xpv = g_xp[(b*TT + 0)*HH + i];
    int buf = 0;
    for (int t = 0; t < TT; t++) {
        float xnext = (t < TT-1) ? g_xp[(b*TT + t + 1)*HH + i] : 0.f;

        const ulonglong2* hp =
            reinterpret_cast<const ulonglong2*>(&h_sh[buf][q*32]);
        unsigned long long a0 = 0ull, a1 = 0ull, a2 = 0ull, a3 = 0ull;
#pragma unroll
        for (int u = 0; u < 8; u += 2) {
            ulonglong2 h0 = hp[u];
            ulonglong2 h1 = hp[u+1];
            a0 = fma2(wv[2*u+0], h0.x, a0);
            a1 = fma2(wv[2*u+1], h0.y, a1);
            a2 = fma2(wv[2*u+2], h1.x, a2);
            a3 = fma2(wv[2*u+3], h1.y, a3);
        }
        a0 = add2(a0, a2);
        a1 = add2(a1, a3);
        a0 = add2(a0, a1);
        float2 f = unpack2(a0);
        float p = f.x + f.y;
        p += __shfl_xor_sync(0xffffffffu, p, 1);
        p += __shfl_xor_sync(0xffffffffu, p, 2);

        if (q == 0) {
            float hn = tanhf(xpv + p);
            h_sh[buf ^ 1][i] = hn;
            g_rnn[(b*TT + t)*HH + i] = hn;
        }
        xpv = xnext;
        buf ^= 1;
        __syncthreads();
    }
    if (q == 0) hid_out[b*HH + i] = h_sh[buf][i];
}

// -------------------- K3: q/k projections (8 rows per block) ----------------
__global__ void k_qk(const float* __restrict__ W1,
                     const float* __restrict__ W2) {
    int n0 = blockIdx.x * 8;
    int i  = threadIdx.x;
    __shared__ __align__(16) float rows[8][HH];
#pragma unroll
    for (int r = 0; r < 8; r++) rows[r][i] = g_rnn[(n0 + r)*HH + i];
    __syncthreads();

    float qa[8], ka[8];
#pragma unroll
    for (int r = 0; r < 8; r++) { qa[r] = 0.f; ka[r] = 0.f; }

    const float4* w1 = (const float4*)(W1 + i*HH);
    const float4* w2 = (const float4*)(W2 + i*HH);
    for (int j = 0; j < HH/4; j++) {
        float4 a = w1[j];
        float4 c = w2[j];
#pragma unroll
        for (int r = 0; r < 8; r++) {
            float4 rr = *(const float4*)&rows[r][j*4];
            qa[r] += a.x*rr.x + a.y*rr.y + a.z*rr.z + a.w*rr.w;
            ka[r] += c.x*rr.x + c.y*rr.y + c.z*rr.z + c.w*rr.w;
        }
    }
#pragma unroll
    for (int r = 0; r < 8; r++) {
        g_q[(n0 + r)*HH + i] = qa[r];
        g_k[(n0 + r)*HH + i] = ka[r];
    }
}

// -------------------- K4: attention row (scores + softmax + context) --------
// grid(T, B), block(256).  One block per (b,t) query row. Causal: s<=t only.
__global__ void k_attn(const float* __restrict__ vvec,
                       float* __restrict__ wout) {
    int t = blockIdx.x, b = blockIdx.y;
    int tid = threadIdx.x, lane = tid & 31, w = tid >> 5;

    __shared__ __align__(16) float qrow[HH], vsh[HH];
    __shared__ float sc[TT];
    __shared__ float red[8];
    __shared__ float stat;
    __shared__ float cpart[2][HH];

    if (tid < HH) {
        qrow[tid] = g_q[(b*TT + t)*HH + tid];
        vsh[tid]  = vvec[tid];
    }
    __syncthreads();

    float4 q4 = *(const float4*)&qrow[lane*4];
    float4 v4 = *(const float4*)&vsh[lane*4];

    // scores: one warp per key position s
    for (int s = w; s <= t; s += 8) {
        float4 kk = *(const float4*)(g_k + (b*TT + s)*HH + lane*4);
        float val = tanhf(q4.x + kk.x) * v4.x
                  + tanhf(q4.y + kk.y) * v4.y
                  + tanhf(q4.z + kk.z) * v4.z
                  + tanhf(q4.w + kk.w) * v4.w;
#pragma unroll
        for (int o = 16; o > 0; o >>= 1)
            val += __shfl_xor_sync(0xffffffffu, val, o);
        if (lane == 0) sc[s] = val;
    }
    __syncthreads();

    // softmax over sc[0..t]
    float m = -1e30f;
    for (int s = tid; s <= t; s += 256) m = fmaxf(m, sc[s]);
#pragma unroll
    for (int o = 16; o > 0; o >>= 1)
        m = fmaxf(m, __shfl_xor_sync(0xffffffffu, m, o));
    if (lane == 0) red[w] = m;
    __syncthreads();
    if (tid == 0) {
        float mm = red[0];
        for (int j = 1; j < 8; j++) mm = fmaxf(mm, red[j]);
        stat = mm;
    }
    __syncthreads();
    float mx = stat;

    float sum = 0.f;
    for (int s = tid; s <= t; s += 256) {
        float e = expf(sc[s] - mx);
        sc[s] = e;
        sum += e;
    }
#pragma unroll
    for (int o = 16; o > 0; o >>= 1)
        sum += __shfl_xor_sync(0xffffffffu, sum, o);
    if (lane == 0) red[w] = sum;
    __syncthreads();
    if (tid == 0) {
        float ss = 0.f;
        for (int j = 0; j < 8; j++) ss += red[j];
        stat = ss;
    }
    __syncthreads();
    float inv = 1.f / stat;

    // write weights row (zeros above the diagonal), normalize in-place
    for (int s = tid; s < TT; s += 256) {
        float wt = (s <= t) ? sc[s] * inv : 0.f;
        wout[((long long)(b*TT + t))*TT + s] = wt;
        if (s <= t) sc[s] = wt;
    }
    __syncthreads();

    // context[b,t,h] = sum_s w[s]*rnn[b,s,h]
    int half = tid >> 7, h = tid & (HH - 1);
    float acc = 0.f;
    for (int s = half; s <= t; s += 2)
        acc += sc[s] * g_rnn[(b*TT + s)*HH + h];
    cpart[half][h] = acc;
    __syncthreads();
    if (tid < HH)
        g_ctx[(b*TT + t)*HH + tid] = cpart[0][tid] + cpart[1][tid];
}

// -------------------- K5: combined projection + relu ------------------------
// out2[n,i] = relu( [rnn|ctx][n,:] . Wp[i,:] + bp[i] ),  8 rows per block
__global__ void k_proj(const float* __restrict__ Wp,
                       const float* __restrict__ bp) {
    int n0 = blockIdx.x * 8;
    int i  = threadIdx.x;
    __shared__ __align__(16) float comb[8][2*HH];
#pragma unroll
    for (int r = 0; r < 8; r++) {
        comb[r][i]      = g_rnn[(n0 + r)*HH + i];
        comb[r][HH + i] = g_ctx[(n0 + r)*HH + i];
    }
    __syncthreads();

    float acc[8];
    float bias = bp[i];
#pragma unroll
    for (int r = 0; r < 8; r++) acc[r] = bias;

    const float4* wp = (const float4*)(Wp + i * 2*HH);
    for (int j = 0; j < (2*HH)/4; j++) {
        float4 a = wp[j];
#pragma unroll
        for (int r = 0; r < 8; r++) {
            float4 cc = *(const float4*)&comb[r][j*4];
            acc[r] += a.x*cc.x + a.y*cc.y + a.z*cc.z + a.w*cc.w;
        }
    }
#pragma unroll
    for (int r = 0; r < 8; r++)
        g_out2[(n0 + r)*HH + i] = fmaxf(acc[r], 0.f);
}

// -------------------- K6: final FC  logits = out2 @ Wfc^T + bfc -------------
// 64 (rows) x 128 (vocab) tile, K=128 fully resident in smem.
// Inner loop uses packed fma.rn.f32x2 (2 MAC per lane-op).
#define FC_AP 68     // At row stride (pad: 4*68 mod 32 = 16 -> 2-way max)
#define FC_BP 132    // Bt row stride (4*132 mod 32 = 16 -> 2-way max)
#define FC_SMEM ((128*FC_AP + 128*FC_BP) * 4)   // 102400 bytes

__global__ void __launch_bounds__(256, 2)
k_fc(const float* __restrict__ Wfc,
     const float* __restrict__ bfc,
     float* __restrict__ logits) {
    extern __shared__ float sm[];
    float* At = sm;                 // [128 k][FC_AP], rows 0..63 used
    float* Bt = sm + 128*FC_AP;     // [128 k][FC_BP], cols 0..127 used

    int tid = threadIdx.x;
    int tx = tid & 15;              // col group: 8 vocab cols
    int ty = tid >> 4;              // row group: 4 rows
    int cb = blockIdx.x * 128;      // vocab tile base
    int rb = blockIdx.y * 64;       // row tile base

    // load A (out2) tile transposed: At[k][r]
    {
        int kq = tid & 31;          // float4 index along k
        int rr = tid >> 5;          // 8 rows per pass
#pragma unroll
        for (int p = 0; p < 8; p++) {
            int row = rr + p*8;
            float4 av = *(const float4*)(g_out2 + (rb + row)*HH + kq*4);
            At[(kq*4+0)*FC_AP + row] = av.x;
            At[(kq*4+1)*FC_AP + row] = av.y;
            At[(kq*4+2)*FC_AP + row] = av.z;
            At[(kq*4+3)*FC_AP + row] = av.w;
        }
        // load B (Wfc) tile transposed: Bt[k][c]
#pragma unroll
        for (int p = 0; p < 16; p++) {
            int vrow = rr + p*8;
            float4 bv = *(const float4*)(Wfc + (long long)(cb + vrow)*HH + kq*4);
            Bt[(kq*4+0)*FC_BP + vrow] = bv.x;
            Bt[(kq*4+1)*FC_BP + vrow] = bv.y;
            Bt[(kq*4+2)*FC_BP + vrow] = bv.z;
            Bt[(kq*4+3)*FC_BP + vrow] = bv.w;
        }
    }
    __syncthreads();

    int r0 = ty * 4;
    int c0 = tx * 8;

    unsigned long long acc[4][4];
#pragma unroll
    for (int r = 0; r < 4; r++)
#pragma unroll
        for (int c = 0; c < 4; c++) acc[r][c] = 0ull;

#pragma unroll 4
    for (int kk = 0; kk < HH; kk++) {
        float4 a = *(const float4*)&At[kk*FC_AP + r0];
        ulonglong2 b01 = *(const ulonglong2*)&Bt[kk*FC_BP + c0];
        ulonglong2 b23 = *(const ulonglong2*)&Bt[kk*FC_BP + c0 + 4];
        unsigned long long ar;
        ar = pack2(a.x, a.x);
        acc[0][0]=fma2(ar,b01.x,acc[0][0]); acc[0][1]=fma2(ar,b01.y,acc[0][1]);
        acc[0][2]=fma2(ar,b23.x,acc[0][2]); acc[0][3]=fma2(ar,b23.y,acc[0][3]);
        ar = pack2(a.y, a.y);
        acc[1][0]=fma2(ar,b01.x,acc[1][0]); acc[1][1]=fma2(ar,b01.y,acc[1][1]);
        acc[1][2]=fma2(ar,b23.x,acc[1][2]); acc[1][3]=fma2(ar,b23.y,acc[1][3]);
        ar = pack2(a.z, a.z);
        acc[2][0]=fma2(ar,b01.x,acc[2][0]); acc[2][1]=fma2(ar,b01.y,acc[2][1]);
        acc[2][2]=fma2(ar,b23.x,acc[2][2]); acc[2][3]=fma2(ar,b23.y,acc[2][3]);
        ar = pack2(a.w, a.w);
        acc[3][0]=fma2(ar,b01.x,acc[3][0]); acc[3][1]=fma2(ar,b01.y,acc[3][1]);
        acc[3][2]=fma2(ar,b23.x,acc[3][2]); acc[3][3]=fma2(ar,b23.y,acc[3][3]);
    }

    float4 bf0 = *(const float4*)(bfc + cb + c0);
    float4 bf1 = *(const float4*)(bfc + cb + c0 + 4);
#pragma unroll
    for (int r = 0; r < 4; r++) {
        long long row = rb + r0 + r;
        float2 p0 = unpack2(acc[r][0]);
        float2 p1 = unpack2(acc[r][1]);
        float2 p2 = unpack2(acc[r][2]);
        float2 p3 = unpack2(acc[r][3]);
        float4 o0 = make_float4(p0.x + bf0.x, p0.y + bf0.y,
                                p1.x + bf0.z, p1.y + bf0.w);
        float4 o1 = make_float4(p2.x + bf1.x, p2.y + bf1.y,
                                p3.x + bf1.z, p3.y + bf1.w);
        float* dst = logits + row * VV + cb + c0;
        *(float4*)(dst)     = o0;
        *(float4*)(dst + 4) = o1;
    }
}

// -------------------- launcher ----------------------------------------------
extern "C" void kernel_launch(void* const* d_in, const int* in_sizes, int n_in,
                              void* d_out, int out_size) {
    const void*  x      = d_in[0];
    const float* hidden = (const float*)d_in[1];
    const float* emb    = (const float*)d_in[2];
    const float* W_ih   = (const float*)d_in[3];
    const float* W_hh   = (const float*)d_in[4];
    const float* b_ih   = (const float*)d_in[5];
    const float* b_hh   = (const float*)d_in[6];
    const float* W1     = (const float*)d_in[7];
    const float* W2     = (const float*)d_in[8];
    const float* v      = (const float*)d_in[9];
    const float* Wp     = (const float*)d_in[10];
    const float* bp     = (const float*)d_in[11];
    const float* Wfc    = (const float*)d_in[12];
    const float* bfc    = (const float*)d_in[13];

    float* out     = (float*)d_out;
    float* logits  = out;
    float* hid_out = out + HID_OFF;
    float* w_out   = out + W_OFF;

    cudaFuncSetAttribute(k_fc, cudaFuncAttributeMaxDynamicSharedMemorySize,
                         FC_SMEM);

    k_detect<<<1, 32>>>((const int*)x);
    k_embed <<<NN, HH>>>(x, emb, W_ih, b_ih, b_hh);
    k_rnn   <<<BB, 512>>>(W_hh, hidden, hid_out);
    k_qk    <<<NN/8, HH>>>(W1, W2);
    k_attn  <<<dim3(TT, BB), 256>>>(v, w_out);
    k_proj  <<<NN/8, HH>>>(Wp, bp);
    k_fc    <<<dim3(VV/128, NN/64), 256, FC_SMEM>>>(Wfc, bfc, logits);
}

// round 12
// speedup vs baseline: 1.2431x; 1.2431x over previous
#include <cuda_runtime.h>
#include <cuda_bf16.h>
#include <math.h>

// Problem constants
#define BB 2
#define TT 512
#define HH 128
#define EE 32
#define VV 32000
#define NN (BB*TT)          // 1024

#define LOGITS_ELEMS ((long long)BB*TT*VV)   // 32768000
#define HID_OFF LOGITS_ELEMS
#define W_OFF   (LOGITS_ELEMS + (long long)BB*HH)  // 32768256

// -------------------- scratch (device globals; no allocation allowed) ------
__device__ float g_xp   [NN*HH];
__device__ float g_rnn  [NN*HH];
__device__ float g_q    [NN*HH];
__device__ float g_kT   [HH*NN];       // transposed: kT[h][n]
__device__ float g_ctx  [NN*HH];
__device__ float g_out2T[HH*NN];       // transposed: out2T[k][n]
__device__ float g_W1T  [HH*HH];
__device__ float g_W2T  [HH*HH];
__device__ float g_WpT  [2*HH*HH];
__device__ float g_WfcT [HH*VV];       // 16.4 MB
__device__ int   g_is64;

// -------------------- packed f32x2 helpers ---------------------------------
__device__ __forceinline__ unsigned long long pack2(float lo, float hi) {
    unsigned long long r;
    asm("mov.b64 %0, {%1,%2};" : "=l"(r) : "f"(lo), "f"(hi));
    return r;
}
__device__ __forceinline__ unsigned long long fma2(unsigned long long a,
                                                   unsigned long long b,
                                                   unsigned long long c) {
    unsigned long long d;
    asm("fma.rn.f32x2 %0, %1, %2, %3;" : "=l"(d) : "l"(a), "l"(b), "l"(c));
    return d;
}
__device__ __forceinline__ unsigned long long add2(unsigned long long a,
                                                   unsigned long long b) {
    unsigned long long d;
    asm("add.rn.f32x2 %0, %1, %2;" : "=l"(d) : "l"(a), "l"(b));
    return d;
}
__device__ __forceinline__ float2 unpack2(unsigned long long v) {
    float2 f;
    asm("mov.b64 {%0,%1}, %2;" : "=f"(f.x), "=f"(f.y) : "l"(v));
    return f;
}

// -------------------- K0: detect int64 vs int32 storage of x ---------------
__global__ void k_detect(const int* __restrict__ x32) {
    int tid = threadIdx.x;
    int bad = 0;
    for (int j = tid; j < 512; j += 32)
        if (x32[2*j + 1] != 0) bad = 1;
    unsigned m = __ballot_sync(0xffffffffu, bad);
    if (tid == 0) g_is64 = (m == 0) ? 1 : 0;
}

// -------------------- Ktr: tiled transpose  dst[N][M] = src[M][N]^T --------
__global__ void k_transpose(const float* __restrict__ src,
                            float* __restrict__ dst, int M, int N) {
    __shared__ float tile[32][33];
    int bx = blockIdx.x * 32;   // N dim
    int by = blockIdx.y * 32;   // M dim
    int x = threadIdx.x, y = threadIdx.y;   // 32 x 8
#pragma unroll
    for (int dy = 0; dy < 32; dy += 8) {
        int m = by + y + dy, n = bx + x;
        if (m < M && n < N) tile[y + dy][x] = src[(long long)m * N + n];
    }
    __syncthreads();
#pragma unroll
    for (int dy = 0; dy < 32; dy += 8) {
        int n = bx + y + dy, m = by + x;
        if (n < N && m < M) dst[(long long)n * M + m] = tile[x][y + dy];
    }
}

// -------------------- K1: embedding gather + input projection --------------
__global__ void k_embed(const void* __restrict__ x,
                        const float* __restrict__ emb_t,
                        const float* __restrict__ W_ih,
                        const float* __restrict__ b_ih,
                        const float* __restrict__ b_hh) {
    int n = blockIdx.x;
    int i = threadIdx.x;
    __shared__ __align__(16) float e_sh[EE];
    if (i < EE) {
        long long idx = g_is64 ? ((const long long*)x)[n]
                               : (long long)((const int*)x)[n];
        e_sh[i] = emb_t[idx * EE + i];
    }
    __syncthreads();
    float acc = b_ih[i] + b_hh[i];
    const float4* w = (const float4*)(W_ih + i * EE);
#pragma unroll
    for (int u = 0; u < EE/4; u++) {
        float4 wv = w[u];
        acc += wv.x * e_sh[4*u+0] + wv.y * e_sh[4*u+1]
             + wv.z * e_sh[4*u+2] + wv.w * e_sh[4*u+3];
    }
    g_xp[n * HH + i] = acc;
}

// -------------------- K2: sequential RNN scan (unchanged, known-good) ------
__global__ void k_rnn(const float* __restrict__ W_hh,
                      const float* __restrict__ hidden,
                      float* __restrict__ hid_out) {
    int b   = blockIdx.x;
    int tid = threadIdx.x;
    int i   = tid >> 2;       // output index 0..127
    int q   = tid & 3;        // lane within output (32 MACs each)

    __shared__ __align__(16) float h_sh[2][HH];

    const unsigned long long* wrow =
        reinterpret_cast<const unsigned long long*>(W_hh + i*HH + q*32);
    unsigned long long wv[16];
#pragma unroll
    for (int r = 0; r < 16; r++) wv[r] = wrow[r];

    if (q == 0) h_sh[0][i] = hidden[b*HH + i];
    __syncthreads();

    float xpv = g_xp[(b*TT + 0)*HH + i];
    int buf = 0;
    for (int t = 0; t < TT; t++) {
        float xnext = (t < TT-1) ? g_xp[(b*TT + t + 1)*HH + i] : 0.f;

        const ulonglong2* hp =
            reinterpret_cast<const ulonglong2*>(&h_sh[buf][q*32]);
        unsigned long long a0 = 0ull, a1 = 0ull, a2 = 0ull, a3 = 0ull;
#pragma unroll
        for (int u = 0; u < 8; u += 2) {
            ulonglong2 h0 = hp[u];
            ulonglong2 h1 = hp[u+1];
            a0 = fma2(wv[2*u+0], h0.x, a0);
            a1 = fma2(wv[2*u+1], h0.y, a1);
            a2 = fma2(wv[2*u+2], h1.x, a2);
            a3 = fma2(wv[2*u+3], h1.y, a3);
        }
        a0 = add2(a0, a2);
        a1 = add2(a1, a3);
        a0 = add2(a0, a1);
        float2 f = unpack2(a0);
        float p = f.x + f.y;
        p += __shfl_xor_sync(0xffffffffu, p, 1);
        p += __shfl_xor_sync(0xffffffffu, p, 2);

        if (q == 0) {
            float hn = tanhf(xpv + p);
            h_sh[buf ^ 1][i] = hn;
            g_rnn[(b*TT + t)*HH + i] = hn;
        }
        xpv = xnext;
        buf ^= 1;
        __syncthreads();
    }
    if (q == 0) hid_out[b*HH + i] = h_sh[buf][i];
}

// -------------------- K3: q/k projections (transposed weights) -------------
// 8 rnn rows per block; 256 threads: half 0 -> q (W1T), half 1 -> kT (W2T).
// Weight loads are lane-coalesced: WT[j*HH + i], lanes over i.
#define QK_R 8
__global__ void k_qk(const float* __restrict__ W1T,
                     const float* __restrict__ W2T) {
    int n0  = blockIdx.x * QK_R;
    int tid = threadIdx.x;                       // 256
    __shared__ __align__(16) float rT[HH * 12];  // rT[j*12 + r]

    for (int idx = tid; idx < QK_R * HH; idx += 256) {
        int j = idx & 127, r = idx >> 7;
        rT[j*12 + r] = g_rnn[(n0 + r)*HH + j];
    }
    __syncthreads();

    int i     = tid & 127;
    int which = tid >> 7;
    const float* WT = which ? W2T : W1T;

    float acc[QK_R];
#pragma unroll
    for (int r = 0; r < QK_R; r++) acc[r] = 0.f;

#pragma unroll 4
    for (int j = 0; j < HH; j++) {
        float wv = WT[j*HH + i];
        float4 r0 = *(const float4*)&rT[j*12];
        float4 r1 = *(const float4*)&rT[j*12 + 4];
        acc[0] += wv*r0.x; acc[1] += wv*r0.y;
        acc[2] += wv*r0.z; acc[3] += wv*r0.w;
        acc[4] += wv*r1.x; acc[5] += wv*r1.y;
        acc[6] += wv*r1.z; acc[7] += wv*r1.w;
    }
    if (which == 0) {
#pragma unroll
        for (int r = 0; r < QK_R; r++) g_q[(n0 + r)*HH + i] = acc[r];
    } else {
#pragma unroll
        for (int r = 0; r < QK_R; r++) g_kT[i*NN + n0 + r] = acc[r];
    }
}

// -------------------- K4: attention row (scores + softmax + context) --------
// grid(T, B), block(256). Scores: one THREAD per key position s (no reduces),
// reading the transposed K so loads are lane-coalesced.
__global__ void k_attn(const float* __restrict__ vvec,
                       float* __restrict__ wout) {
    int t = blockIdx.x, b = blockIdx.y;
    int tid = threadIdx.x, lane = tid & 31, w = tid >> 5;

    __shared__ __align__(16) float qrow[HH], vsh[HH];
    __shared__ float sc[TT];
    __shared__ float red[8];
    __shared__ float stat;
    __shared__ float cpart[2][HH];

    if (tid < HH) {
        qrow[tid] = g_q[(b*TT + t)*HH + tid];
        vsh[tid]  = vvec[tid];
    }
    __syncthreads();

    // scores: thread s computes full dot over h
    for (int s = tid; s <= t; s += 256) {
        const float* kc = g_kT + b*TT + s;
        float a0 = 0.f, a1 = 0.f, a2 = 0.f, a3 = 0.f;
#pragma unroll 4
        for (int h = 0; h < HH; h += 4) {
            float4 qq = *(const float4*)&qrow[h];
            float4 vv = *(const float4*)&vsh[h];
            a0 += tanhf(qq.x + kc[(h+0)*NN]) * vv.x;
            a1 += tanhf(qq.y + kc[(h+1)*NN]) * vv.y;
            a2 += tanhf(qq.z + kc[(h+2)*NN]) * vv.z;
            a3 += tanhf(qq.w + kc[(h+3)*NN]) * vv.w;
        }
        sc[s] = (a0 + a1) + (a2 + a3);
    }
    __syncthreads();

    // softmax over sc[0..t]
    float m = -1e30f;
    for (int s = tid; s <= t; s += 256) m = fmaxf(m, sc[s]);
#pragma unroll
    for (int o = 16; o > 0; o >>= 1)
        m = fmaxf(m, __shfl_xor_sync(0xffffffffu, m, o));
    if (lane == 0) red[w] = m;
    __syncthreads();
    if (tid == 0) {
        float mm = red[0];
        for (int j = 1; j < 8; j++) mm = fmaxf(mm, red[j]);
        stat = mm;
    }
    __syncthreads();
    float mx = stat;

    float sum = 0.f;
    for (int s = tid; s <= t; s += 256) {
        float e = expf(sc[s] - mx);
        sc[s] = e;
        sum += e;
    }
#pragma unroll
    for (int o = 16; o > 0; o >>= 1)
        sum += __shfl_xor_sync(0xffffffffu, sum, o);
    if (lane == 0) red[w] = sum;
    __syncthreads();
    if (tid == 0) {
        float ss = 0.f;
        for (int j = 0; j < 8; j++) ss += red[j];
        stat = ss;
    }
    __syncthreads();
    float inv = 1.f / stat;

    for (int s = tid; s < TT; s += 256) {
        float wt = (s <= t) ? sc[s] * inv : 0.f;
        wout[((long long)(b*TT + t))*TT + s] = wt;
        if (s <= t) sc[s] = wt;
    }
    __syncthreads();

    // context[b,t,h] = sum_s w[s]*rnn[b,s,h]
    int half = tid >> 7, h = tid & (HH - 1);
    float acc = 0.f;
    for (int s = half; s <= t; s += 2)
        acc += sc[s] * g_rnn[(b*TT + s)*HH + h];
    cpart[half][h] = acc;
    __syncthreads();
    if (tid < HH)
        g_ctx[(b*TT + t)*HH + tid] = cpart[0][tid] + cpart[1][tid];
}

// -------------------- K5: combined projection + relu (transposed Wp) -------
// 8 rows per block, 128 threads (thread = output channel i).
// Writes out2 TRANSPOSED (out2T[k][n]) for the FC kernel.
__global__ void k_proj(const float* __restrict__ WpT,
                       const float* __restrict__ bp) {
    int n0  = blockIdx.x * QK_R;
    int tid = threadIdx.x;                            // 128
    __shared__ __align__(16) float cT[2*HH * 12];     // cT[j*12 + r]

    for (int idx = tid; idx < QK_R * 2*HH; idx += 128) {
        int j = idx & 255, r = idx >> 8;
        float v = (j < HH) ? g_rnn[(n0 + r)*HH + j]
                           : g_ctx[(n0 + r)*HH + (j - HH)];
        cT[j*12 + r] = v;
    }
    __syncthreads();

    int i = tid;
    float bias = bp[i];
    float acc[QK_R];
#pragma unroll
    for (int r = 0; r < QK_R; r++) acc[r] = bias;

#pragma unroll 4
    for (int j = 0; j < 2*HH; j++) {
        float wv = WpT[j*HH + i];
        float4 r0 = *(const float4*)&cT[j*12];
        float4 r1 = *(const float4*)&cT[j*12 + 4];
        acc[0] += wv*r0.x; acc[1] += wv*r0.y;
        acc[2] += wv*r0.z; acc[3] += wv*r0.w;
        acc[4] += wv*r1.x; acc[5] += wv*r1.y;
        acc[6] += wv*r1.z; acc[7] += wv*r1.w;
    }
#pragma unroll
    for (int r = 0; r < QK_R; r++)
        g_out2T[i*NN + n0 + r] = fmaxf(acc[r], 0.f);
}

// -------------------- K6: final FC  logits = out2 @ Wfc^T + bfc -------------
// 128x128 block tile, K=128 resident. Per-thread 8x8 f32x2 tile.
// Conflict-free smem (k-major, broadcast reads) + coalesced gmem (transposed
// sources). FFMA2-bound.
#define FCD 128
#define FC_SMEM (2*FCD*FCD*4)    // 131072 bytes

__global__ void __launch_bounds__(256, 1)
k_fc(const float* __restrict__ WfcT,
     const float* __restrict__ bfc,
     float* __restrict__ logits) {
    extern __shared__ float sm[];
    float* As = sm;              // As[k][r]  (k-major)
    float* Bs = sm + FCD*FCD;    // Bs[k][c]

    int tid = threadIdx.x;
    int cb = blockIdx.x * FCD;
    int rb = blockIdx.y * FCD;

    {   // coalesced loads, conflict-free stores
        int k0 = tid >> 5;       // 0..7
        int q4 = tid & 31;       // float4 index within row
#pragma unroll
        for (int p = 0; p < 16; p++) {
            int kk = k0 + p*8;
            *(float4*)&As[kk*FCD + q4*4] =
                *(const float4*)(g_out2T + kk*NN + rb + q4*4);
            *(float4*)&Bs[kk*FCD + q4*4] =
                *(const float4*)(WfcT + (long long)kk*VV + cb + q4*4);
        }
    }
    __syncthreads();

    int w = tid >> 5, l = tid & 31;
    int rBase = (w & 3)*32 + (l >> 3)*8;   // 4 warp-rows x (4 rowgroups x 8)
    int cBase = (w >> 2)*64 + (l & 7)*8;   // 2 warp-cols x (8 colgroups x 8)

    unsigned long long acc[8][4];
#pragma unroll
    for (int r = 0; r < 8; r++)
#pragma unroll
        for (int c = 0; c < 4; c++) acc[r][c] = 0ull;

#pragma unroll 4
    for (int kk = 0; kk < FCD; kk++) {
        float4 a0 = *(const float4*)&As[kk*FCD + rBase];
        float4 a1 = *(const float4*)&As[kk*FCD + rBase + 4];
        ulonglong2 b0 = *(const ulonglong2*)&Bs[kk*FCD + cBase];
        ulonglong2 b1 = *(const ulonglong2*)&Bs[kk*FCD + cBase + 4];
        float av[8] = {a0.x, a0.y, a0.z, a0.w, a1.x, a1.y, a1.z, a1.w};
#pragma unroll
        for (int r = 0; r < 8; r++) {
            unsigned long long ar = pack2(av[r], av[r]);
            acc[r][0] = fma2(ar, b0.x, acc[r][0]);
            acc[r][1] = fma2(ar, b0.y, acc[r][1]);
            acc[r][2] = fma2(ar, b1.x, acc[r][2]);
            acc[r][3] = fma2(ar, b1.y, acc[r][3]);
        }
    }

    float4 bf0 = *(const float4*)(bfc + cb + cBase);
    float4 bf1 = *(const float4*)(bfc + cb + cBase + 4);
#pragma unroll
    for (int r = 0; r < 8; r++) {
        float2 p0 = unpack2(acc[r][0]);
        float2 p1 = unpack2(acc[r][1]);
        float2 p2 = unpack2(acc[r][2]);
        float2 p3 = unpack2(acc[r][3]);
        float4 o0 = make_float4(p0.x + bf0.x, p0.y + bf0.y,
                                p1.x + bf0.z, p1.y + bf0.w);
        float4 o1 = make_float4(p2.x + bf1.x, p2.y + bf1.y,
                                p3.x + bf1.z, p3.y + bf1.w);
        float* dst = logits + (long long)(rb + rBase + r)*VV + cb + cBase;
        *(float4*)(dst)     = o0;
        *(float4*)(dst + 4) = o1;
    }
}

// -------------------- launcher ----------------------------------------------
extern "C" void kernel_launch(void* const* d_in, const int* in_sizes, int n_in,
                              void* d_out, int out_size) {
    const void*  x      = d_in[0];
    const float* hidden = (const float*)d_in[1];
    const float* emb    = (const float*)d_in[2];
    const float* W_ih   = (const float*)d_in[3];
    const float* W_hh   = (const float*)d_in[4];
    const float* b_ih   = (const float*)d_in[5];
    const float* b_hh   = (const float*)d_in[6];
    const float* W1     = (const float*)d_in[7];
    const float* W2     = (const float*)d_in[8];
    const float* v      = (const float*)d_in[9];
    const float* Wp     = (const float*)d_in[10];
    const float* bp     = (const float*)d_in[11];
    const float* Wfc    = (const float*)d_in[12];
    const float* bfc    = (const float*)d_in[13];

    float* out     = (float*)d_out;
    float* logits  = out;
    float* hid_out = out + HID_OFF;
    float* w_out   = out + W_OFF;

    float *dW1T, *dW2T, *dWpT, *dWfcT;
    cudaGetSymbolAddress((void**)&dW1T,  g_W1T);
    cudaGetSymbolAddress((void**)&dW2T,  g_W2T);
    cudaGetSymbolAddress((void**)&dWpT,  g_WpT);
    cudaGetSymbolAddress((void**)&dWfcT, g_WfcT);

    cudaFuncSetAttribute(k_fc, cudaFuncAttributeMaxDynamicSharedMemorySize,
                         FC_SMEM);

    dim3 tb(32, 8);
    k_detect   <<<1, 32>>>((const int*)x);
    k_transpose<<<dim3(4,    4), tb>>>(W1,  dW1T,  HH, HH);
    k_transpose<<<dim3(8,    4), tb>>>(Wp,  dWpT,  HH, 2*HH);
    k_transpose<<<dim3(4,    4), tb>>>(W2,  dW2T,  HH, HH);
    k_transpose<<<dim3(4, 1000), tb>>>(Wfc, dWfcT, VV, HH);
    k_embed    <<<NN, HH>>>(x, emb, W_ih, b_ih, b_hh);
    k_rnn      <<<BB, 512>>>(W_hh, hidden, hid_out);
    k_qk       <<<NN/QK_R, 256>>>(dW1T, dW2T);
    k_attn     <<<dim3(TT, BB), 256>>>(v, w_out);
    k_proj     <<<NN/QK_R, 128>>>(dWpT, bp);
    k_fc       <<<dim3(VV/FCD, NN/FCD), 256, FC_SMEM>>>(dWfcT, bfc, logits);
}